// round 1
// baseline (speedup 1.0000x reference)
#include <cuda_runtime.h>

#define N_NODES   100000
#define N_FEAT    128
#define N_CLASSES 40
#define N_EDGES   1600000
#define C4        10   // float4 chunks per 40-float row

// Scratch (static device globals — no allocation in kernel_launch)
__device__ float g_bufA[N_NODES * N_CLASSES];
__device__ float g_bufB[N_NODES * N_CLASSES];
__device__ float g_dinv[N_NODES];
__device__ int   g_deg[N_NODES];

__global__ void k_zero_deg() {
    int i = blockIdx.x * blockDim.x + threadIdx.x;
    if (i < N_NODES) g_deg[i] = 0;
}

__global__ void k_deg(const int* __restrict__ dst) {
    int e = blockIdx.x * blockDim.x + threadIdx.x;
    if (e < N_EDGES) atomicAdd(&g_deg[dst[e]], 1);
}

__global__ void k_dinv() {
    int i = blockIdx.x * blockDim.x + threadIdx.x;
    if (i < N_NODES) g_dinv[i] = rsqrtf((float)(g_deg[i] + 1));  // +1 = self loop
}

// g_bufA = x @ W   ([N,128] x [128,40]); W staged in smem as float4.
__global__ void k_matmul(const float* __restrict__ x, const float* __restrict__ W) {
    __shared__ float4 Ws[N_FEAT * C4];  // 128*40 floats = 20KB
    for (int i = threadIdx.x; i < N_FEAT * C4; i += blockDim.x)
        Ws[i] = reinterpret_cast<const float4*>(W)[i];
    __syncthreads();
    int n = blockIdx.x * blockDim.x + threadIdx.x;
    if (n >= N_NODES) return;

    float4 acc[C4];
#pragma unroll
    for (int j = 0; j < C4; j++) acc[j] = make_float4(0.f, 0.f, 0.f, 0.f);

    const float4* xr = reinterpret_cast<const float4*>(x + (size_t)n * N_FEAT);
    for (int k4 = 0; k4 < N_FEAT / 4; k4++) {
        float4 xv = xr[k4];
#pragma unroll
        for (int j = 0; j < 4; j++) {
            float xs = (j == 0) ? xv.x : (j == 1) ? xv.y : (j == 2) ? xv.z : xv.w;
            int k = k4 * 4 + j;
#pragma unroll
            for (int c = 0; c < C4; c++) {
                float4 w = Ws[k * C4 + c];
                acc[c].x += xs * w.x;
                acc[c].y += xs * w.y;
                acc[c].z += xs * w.z;
                acc[c].w += xs * w.w;
            }
        }
    }
    float4* out = reinterpret_cast<float4*>(g_bufA + (size_t)n * N_CLASSES);
#pragma unroll
    for (int c = 0; c < C4; c++) out[c] = acc[c];
}

// out[i] = dinv[i]^2 * in[i]  (self-loop contribution; also inits the buffer)
// ab == 0: A -> B ; ab == 1: B -> A
__global__ void k_selfinit(int ab) {
    int i = blockIdx.x * blockDim.x + threadIdx.x;
    if (i >= N_NODES * C4) return;
    const float4* yin  = reinterpret_cast<const float4*>(ab ? g_bufB : g_bufA);
    float4*       yout = reinterpret_cast<float4*>(ab ? g_bufA : g_bufB);
    int n = i / C4;
    float s = g_dinv[n];
    s *= s;
    float4 v = yin[i];
    v.x *= s; v.y *= s; v.z *= s; v.w *= s;
    yout[i] = v;
}

// out[dst] += dinv[src]*dinv[dst] * in[src]   (vector float4 atomics, sm_90+)
__global__ void k_scatter(int ab, const int* __restrict__ src, const int* __restrict__ dst) {
    int e = blockIdx.x * blockDim.x + threadIdx.x;
    if (e >= N_EDGES) return;
    const float* yin  = ab ? g_bufB : g_bufA;
    float*       yout = ab ? g_bufA : g_bufB;
    int s = src[e];
    int d = dst[e];
    float nrm = g_dinv[s] * g_dinv[d];
    const float4* yi = reinterpret_cast<const float4*>(yin + (size_t)s * N_CLASSES);
    float4*       yo = reinterpret_cast<float4*>(yout + (size_t)d * N_CLASSES);
#pragma unroll
    for (int j = 0; j < C4; j++) {
        float4 v = yi[j];
        v.x *= nrm; v.y *= nrm; v.z *= nrm; v.w *= nrm;
        atomicAdd(yo + j, v);  // RED.E.ADD.F32 x4 (vector red on sm_90+)
    }
}

// out = log_softmax(g_bufA + b)
__global__ void k_logsoftmax(const float* __restrict__ bias, float* __restrict__ out) {
    __shared__ float bs[N_CLASSES];
    if (threadIdx.x < N_CLASSES) bs[threadIdx.x] = bias[threadIdx.x];
    __syncthreads();
    int n = blockIdx.x * blockDim.x + threadIdx.x;
    if (n >= N_NODES) return;

    float v[N_CLASSES];
    const float4* in = reinterpret_cast<const float4*>(g_bufA + (size_t)n * N_CLASSES);
#pragma unroll
    for (int j = 0; j < C4; j++) {
        float4 t = in[j];
        v[4 * j + 0] = t.x + bs[4 * j + 0];
        v[4 * j + 1] = t.y + bs[4 * j + 1];
        v[4 * j + 2] = t.z + bs[4 * j + 2];
        v[4 * j + 3] = t.w + bs[4 * j + 3];
    }
    float m = v[0];
#pragma unroll
    for (int c = 1; c < N_CLASSES; c++) m = fmaxf(m, v[c]);
    float sum = 0.f;
#pragma unroll
    for (int c = 0; c < N_CLASSES; c++) sum += expf(v[c] - m);
    float lse = m + logf(sum);

    float4* o = reinterpret_cast<float4*>(out + (size_t)n * N_CLASSES);
#pragma unroll
    for (int j = 0; j < C4; j++) {
        float4 t;
        t.x = v[4 * j + 0] - lse;
        t.y = v[4 * j + 1] - lse;
        t.z = v[4 * j + 2] - lse;
        t.w = v[4 * j + 3] - lse;
        o[j] = t;
    }
}

extern "C" void kernel_launch(void* const* d_in, const int* in_sizes, int n_in,
                              void* d_out, int out_size) {
    const float* x  = (const float*)d_in[0];  // [100000,128]
    const float* W  = (const float*)d_in[1];  // [128,40]
    const float* b  = (const float*)d_in[2];  // [40]
    const int*   ei = (const int*)d_in[3];    // [2,1600000]
    const int* src = ei;
    const int* dst = ei + N_EDGES;
    float* out = (float*)d_out;

    const int TB = 256;
    const int gN  = (N_NODES + TB - 1) / TB;
    const int gE  = (N_EDGES + TB - 1) / TB;
    const int gI  = (N_NODES * C4 + TB - 1) / TB;

    // Normalization
    k_zero_deg<<<gN, TB>>>();
    k_deg<<<gE, TB>>>(dst);
    k_dinv<<<gN, TB>>>();

    // Project to class space FIRST: (A^K x) W == A^K (x W)
    k_matmul<<<gN, TB>>>(x, W);

    // Hop 1: A -> B
    k_selfinit<<<gI, TB>>>(0);
    k_scatter<<<gE, TB>>>(0, src, dst);
    // Hop 2: B -> A
    k_selfinit<<<gI, TB>>>(1);
    k_scatter<<<gE, TB>>>(1, src, dst);

    // logits + log_softmax
    k_logsoftmax<<<gN, TB>>>(b, out);
}

// round 2
// speedup vs baseline: 1.0839x; 1.0839x over previous
#include <cuda_runtime.h>

#define N_NODES   100000
#define N_FEAT    128
#define N_CLASSES 40
#define N_EDGES   1600000
#define C4        10   // float4 chunks per 40-float row
#define CP        20   // f32x2 pairs per 40-float row

// Scratch (static device globals — no allocation in kernel_launch)
__device__ float g_u[N_NODES * N_CLASSES];  // gather source (pre-scaled)
__device__ float g_t[N_NODES * N_CLASSES];  // scatter accumulator
__device__ float g_dinv[N_NODES];
__device__ int   g_deg[N_NODES];

__device__ __forceinline__ unsigned long long pack2(float a, float b) {
    unsigned long long p;
    asm("mov.b64 %0, {%1, %2};" : "=l"(p) : "f"(a), "f"(b));
    return p;
}
__device__ __forceinline__ void unpack2(unsigned long long p, float& a, float& b) {
    asm("mov.b64 {%0, %1}, %2;" : "=f"(a), "=f"(b) : "l"(p));
}
#define FMA_F32X2(d, a, b, c) \
    asm("fma.rn.f32x2 %0, %1, %2, %3;" : "=l"(d) : "l"(a), "l"(b), "l"(c))

__global__ void k_zero_deg() {
    int i = blockIdx.x * blockDim.x + threadIdx.x;
    if (i < N_NODES) g_deg[i] = 0;
}

__global__ void k_deg(const int* __restrict__ dst) {
    int t = blockIdx.x * blockDim.x + threadIdx.x;
    if (t < N_EDGES / 2) {
        int2 d2 = reinterpret_cast<const int2*>(dst)[t];
        atomicAdd(&g_deg[d2.x], 1);
        atomicAdd(&g_deg[d2.y], 1);
    }
}

__global__ void k_dinv() {
    int i = blockIdx.x * blockDim.x + threadIdx.x;
    if (i < N_NODES) g_dinv[i] = rsqrtf((float)(g_deg[i] + 1));  // +1 = self loop
}

// y = x @ W (f32x2 packed FMA), then u = dinv*y ; t = u (scatter accumulator,
// initialized with the self-loop term: dinv * (dinv*y) applied at post-scale).
__global__ void k_matmul(const float* __restrict__ x, const float* __restrict__ W) {
    __shared__ longlong2 Ws[N_FEAT * C4];  // [k][c]: pairs (w0,w1),(w2,w3) packed
    for (int i = threadIdx.x; i < N_FEAT * C4; i += blockDim.x) {
        float4 w = reinterpret_cast<const float4*>(W)[i];
        longlong2 p;
        p.x = (long long)pack2(w.x, w.y);
        p.y = (long long)pack2(w.z, w.w);
        Ws[i] = p;
    }
    __syncthreads();
    int n = blockIdx.x * blockDim.x + threadIdx.x;
    if (n >= N_NODES) return;

    unsigned long long acc[CP];
#pragma unroll
    for (int c = 0; c < CP; c++) acc[c] = 0ull;  // (0.f,0.f)

    const float4* xr = reinterpret_cast<const float4*>(x + (size_t)n * N_FEAT);
#pragma unroll 4
    for (int k4 = 0; k4 < N_FEAT / 4; k4++) {
        float4 xv = xr[k4];
#pragma unroll
        for (int j = 0; j < 4; j++) {
            float xs = (j == 0) ? xv.x : (j == 1) ? xv.y : (j == 2) ? xv.z : xv.w;
            unsigned long long xs2 = pack2(xs, xs);
            int k = k4 * 4 + j;
#pragma unroll
            for (int c = 0; c < C4; c++) {
                longlong2 w = Ws[k * C4 + c];
                FMA_F32X2(acc[2 * c],     xs2, (unsigned long long)w.x, acc[2 * c]);
                FMA_F32X2(acc[2 * c + 1], xs2, (unsigned long long)w.y, acc[2 * c + 1]);
            }
        }
    }

    float di = g_dinv[n];
    float4* up = reinterpret_cast<float4*>(g_u + (size_t)n * N_CLASSES);
    float4* tp = reinterpret_cast<float4*>(g_t + (size_t)n * N_CLASSES);
#pragma unroll
    for (int c = 0; c < C4; c++) {
        float4 v;
        unpack2(acc[2 * c],     v.x, v.y);
        unpack2(acc[2 * c + 1], v.z, v.w);
        v.x *= di; v.y *= di; v.z *= di; v.w *= di;
        up[c] = v;
        tp[c] = v;
    }
}

// Pure scatter-add: t[dst] += u[src]. No per-edge normalization at all.
__global__ void k_scatter(const int* __restrict__ src, const int* __restrict__ dst) {
    int t = blockIdx.x * blockDim.x + threadIdx.x;
    if (t >= N_EDGES / 2) return;
    int2 s2 = reinterpret_cast<const int2*>(src)[t];
    int2 d2 = reinterpret_cast<const int2*>(dst)[t];

    const float4* ga = reinterpret_cast<const float4*>(g_u + (size_t)s2.x * N_CLASSES);
    float4*       oa = reinterpret_cast<float4*>(g_t + (size_t)d2.x * N_CLASSES);
    const float4* gb = reinterpret_cast<const float4*>(g_u + (size_t)s2.y * N_CLASSES);
    float4*       ob = reinterpret_cast<float4*>(g_t + (size_t)d2.y * N_CLASSES);
#pragma unroll
    for (int j = 0; j < C4; j++) atomicAdd(oa + j, ga[j]);
#pragma unroll
    for (int j = 0; j < C4; j++) atomicAdd(ob + j, gb[j]);
}

// Between hops: r1 = dinv*t1 (hop-1 result); u2 = dinv*r1; t2 init = u2.
// => u = t = dinv^2 * t1 (elementwise, in-place safe).
__global__ void k_mid() {
    int i = blockIdx.x * blockDim.x + threadIdx.x;
    if (i >= N_NODES * C4) return;
    int n = i / C4;
    float di = g_dinv[n];
    float s = di * di;
    float4 v = reinterpret_cast<const float4*>(g_t)[i];
    v.x *= s; v.y *= s; v.z *= s; v.w *= s;
    reinterpret_cast<float4*>(g_u)[i] = v;
    reinterpret_cast<float4*>(g_t)[i] = v;
}

// out = log_softmax(dinv*t2 + b)
__global__ void k_logsoftmax(const float* __restrict__ bias, float* __restrict__ out) {
    __shared__ float bs[N_CLASSES];
    if (threadIdx.x < N_CLASSES) bs[threadIdx.x] = bias[threadIdx.x];
    __syncthreads();
    int n = blockIdx.x * blockDim.x + threadIdx.x;
    if (n >= N_NODES) return;

    float di = g_dinv[n];
    float v[N_CLASSES];
    const float4* in = reinterpret_cast<const float4*>(g_t + (size_t)n * N_CLASSES);
#pragma unroll
    for (int j = 0; j < C4; j++) {
        float4 tv = in[j];
        v[4 * j + 0] = tv.x * di + bs[4 * j + 0];
        v[4 * j + 1] = tv.y * di + bs[4 * j + 1];
        v[4 * j + 2] = tv.z * di + bs[4 * j + 2];
        v[4 * j + 3] = tv.w * di + bs[4 * j + 3];
    }
    float m = v[0];
#pragma unroll
    for (int c = 1; c < N_CLASSES; c++) m = fmaxf(m, v[c]);
    float sum = 0.f;
#pragma unroll
    for (int c = 0; c < N_CLASSES; c++) sum += __expf(v[c] - m);
    float lse = m + __logf(sum);

    float4* o = reinterpret_cast<float4*>(out + (size_t)n * N_CLASSES);
#pragma unroll
    for (int j = 0; j < C4; j++) {
        float4 tv;
        tv.x = v[4 * j + 0] - lse;
        tv.y = v[4 * j + 1] - lse;
        tv.z = v[4 * j + 2] - lse;
        tv.w = v[4 * j + 3] - lse;
        o[j] = tv;
    }
}

extern "C" void kernel_launch(void* const* d_in, const int* in_sizes, int n_in,
                              void* d_out, int out_size) {
    const float* x  = (const float*)d_in[0];  // [100000,128]
    const float* W  = (const float*)d_in[1];  // [128,40]
    const float* b  = (const float*)d_in[2];  // [40]
    const int*   ei = (const int*)d_in[3];    // [2,1600000]
    const int* src = ei;
    const int* dst = ei + N_EDGES;
    float* out = (float*)d_out;

    const int TB = 256;
    const int gN  = (N_NODES + TB - 1) / TB;
    const int gE2 = (N_EDGES / 2 + TB - 1) / TB;
    const int gI  = (N_NODES * C4 + TB - 1) / TB;

    k_zero_deg<<<gN, TB>>>();
    k_deg<<<gE2, TB>>>(dst);
    k_dinv<<<gN, TB>>>();

    // Project to class space first: (A^K x) W == A^K (x W)
    k_matmul<<<gN, TB>>>(x, W);

    k_scatter<<<gE2, TB>>>(src, dst);   // hop 1: t += u[src]
    k_mid<<<gI, TB>>>();                // rescale + reinit for hop 2
    k_scatter<<<gE2, TB>>>(src, dst);   // hop 2

    k_logsoftmax<<<gN, TB>>>(b, out);
}

// round 3
// speedup vs baseline: 1.9432x; 1.7927x over previous
#include <cuda_runtime.h>

#define N_NODES   100000
#define N_FEAT    128
#define N_CLASSES 40
#define N_EDGES   1600000
#define C4        10   // float4 chunks per 40-float row
#define CP        20   // f32x2 pairs per 40-float row
#define SCAN_CHUNK 1024
#define NB_SCAN   ((N_NODES + SCAN_CHUNK - 1) / SCAN_CHUNK)  // 98

// Scratch (static device globals — no allocation anywhere)
__device__ float g_u[N_NODES * N_CLASSES];   // gather source (pre-scaled)
__device__ float g_t[N_NODES * N_CLASSES];   // hop result
__device__ float g_dinv[N_NODES];
__device__ int   g_deg[N_NODES];
__device__ int   g_rowptr[N_NODES + 1];
__device__ int   g_cursor[N_NODES];
__device__ int   g_col[N_EDGES];
__device__ int   g_bsum[NB_SCAN];
__device__ int   g_boff[NB_SCAN];

__device__ __forceinline__ unsigned long long pack2(float a, float b) {
    unsigned long long p;
    asm("mov.b64 %0, {%1, %2};" : "=l"(p) : "f"(a), "f"(b));
    return p;
}
__device__ __forceinline__ void unpack2(unsigned long long p, float& a, float& b) {
    asm("mov.b64 {%0, %1}, %2;" : "=f"(a), "=f"(b) : "l"(p));
}
#define FMA_F32X2(d, a, b, c) \
    asm("fma.rn.f32x2 %0, %1, %2, %3;" : "=l"(d) : "l"(a), "l"(b), "l"(c))

// ───────────────────────── degree + normalization ─────────────────────────
__global__ void k_zero_deg() {
    int i = blockIdx.x * blockDim.x + threadIdx.x;
    if (i < N_NODES) g_deg[i] = 0;
}

__global__ void k_deg(const int* __restrict__ dst) {
    int t = blockIdx.x * blockDim.x + threadIdx.x;
    if (t < N_EDGES / 2) {
        int2 d2 = reinterpret_cast<const int2*>(dst)[t];
        atomicAdd(&g_deg[d2.x], 1);
        atomicAdd(&g_deg[d2.y], 1);
    }
}

__global__ void k_dinv() {
    int i = blockIdx.x * blockDim.x + threadIdx.x;
    if (i < N_NODES) g_dinv[i] = rsqrtf((float)(g_deg[i] + 1));  // +1 = self loop
}

// ───────────────────────── CSR build: scan + fill ──────────────────────────
__global__ void k_scan1() {
    __shared__ int sh[256];
    int tid = threadIdx.x;
    int base = blockIdx.x * SCAN_CHUNK + tid * 4;
    int v[4]; int s = 0;
#pragma unroll
    for (int i = 0; i < 4; i++) {
        int idx = base + i;
        v[i] = (idx < N_NODES) ? g_deg[idx] : 0;
        s += v[i];
    }
    int val = s;
    sh[tid] = val; __syncthreads();
#pragma unroll
    for (int off = 1; off < 256; off <<= 1) {
        int add = (tid >= off) ? sh[tid - off] : 0;
        __syncthreads();
        val += add; sh[tid] = val;
        __syncthreads();
    }
    if (tid == 255) g_bsum[blockIdx.x] = val;
    int run = val - s;  // exclusive prefix of this thread's chunk within block
#pragma unroll
    for (int i = 0; i < 4; i++) {
        int idx = base + i;
        if (idx < N_NODES) g_rowptr[idx] = run;
        run += v[i];
    }
}

__global__ void k_scan2() {
    __shared__ int sh[128];
    int tid = threadIdx.x;
    int v = (tid < NB_SCAN) ? g_bsum[tid] : 0;
    int val = v;
    sh[tid] = val; __syncthreads();
#pragma unroll
    for (int off = 1; off < 128; off <<= 1) {
        int add = (tid >= off) ? sh[tid - off] : 0;
        __syncthreads();
        val += add; sh[tid] = val;
        __syncthreads();
    }
    if (tid < NB_SCAN) g_boff[tid] = val - v;  // exclusive
}

__global__ void k_scan3() {
    int i = blockIdx.x * blockDim.x + threadIdx.x;
    if (i < N_NODES) {
        int r = g_rowptr[i] + g_boff[i / SCAN_CHUNK];
        g_rowptr[i] = r;
        g_cursor[i] = r;
    }
    if (i == 0) g_rowptr[N_NODES] = N_EDGES;
}

__global__ void k_fill(const int* __restrict__ src, const int* __restrict__ dst) {
    int t = blockIdx.x * blockDim.x + threadIdx.x;
    if (t >= N_EDGES / 2) return;
    int2 s2 = reinterpret_cast<const int2*>(src)[t];
    int2 d2 = reinterpret_cast<const int2*>(dst)[t];
    int p0 = atomicAdd(&g_cursor[d2.x], 1);
    g_col[p0] = s2.x;
    int p1 = atomicAdd(&g_cursor[d2.y], 1);
    g_col[p1] = s2.y;
}

// ───────────────────────── y = x@W, u=t-source init ────────────────────────
// Two nodes per thread (block-strided) so each smem W read feeds 2 FMAs.
__global__ void __launch_bounds__(256) k_matmul(const float* __restrict__ x,
                                                const float* __restrict__ W) {
    __shared__ longlong2 Ws[N_FEAT * C4];  // [k][c]: (w0,w1),(w2,w3) packed
    for (int i = threadIdx.x; i < N_FEAT * C4; i += blockDim.x) {
        float4 w = reinterpret_cast<const float4*>(W)[i];
        longlong2 p;
        p.x = (long long)pack2(w.x, w.y);
        p.y = (long long)pack2(w.z, w.w);
        Ws[i] = p;
    }
    __syncthreads();
    int n0 = blockIdx.x * 512 + threadIdx.x;   // first node
    int n1 = n0 + 256;                         // second node (block-strided)
    if (n0 >= N_NODES) return;
    bool two = (n1 < N_NODES);

    unsigned long long accA[CP], accB[CP];
#pragma unroll
    for (int c = 0; c < CP; c++) { accA[c] = 0ull; accB[c] = 0ull; }

    const float4* xa = reinterpret_cast<const float4*>(x + (size_t)n0 * N_FEAT);
    const float4* xb = reinterpret_cast<const float4*>(x + (size_t)(two ? n1 : n0) * N_FEAT);
#pragma unroll 2
    for (int k4 = 0; k4 < N_FEAT / 4; k4++) {
        float4 va = xa[k4];
        float4 vb = xb[k4];
#pragma unroll
        for (int j = 0; j < 4; j++) {
            float fa = (j == 0) ? va.x : (j == 1) ? va.y : (j == 2) ? va.z : va.w;
            float fb = (j == 0) ? vb.x : (j == 1) ? vb.y : (j == 2) ? vb.z : vb.w;
            unsigned long long a2 = pack2(fa, fa);
            unsigned long long b2 = pack2(fb, fb);
            int k = k4 * 4 + j;
#pragma unroll
            for (int c = 0; c < C4; c++) {
                longlong2 w = Ws[k * C4 + c];
                FMA_F32X2(accA[2 * c],     a2, (unsigned long long)w.x, accA[2 * c]);
                FMA_F32X2(accA[2 * c + 1], a2, (unsigned long long)w.y, accA[2 * c + 1]);
                FMA_F32X2(accB[2 * c],     b2, (unsigned long long)w.x, accB[2 * c]);
                FMA_F32X2(accB[2 * c + 1], b2, (unsigned long long)w.y, accB[2 * c + 1]);
            }
        }
    }

    float dA = g_dinv[n0];
    float4* uA = reinterpret_cast<float4*>(g_u + (size_t)n0 * N_CLASSES);
#pragma unroll
    for (int c = 0; c < C4; c++) {
        float4 v;
        unpack2(accA[2 * c],     v.x, v.y);
        unpack2(accA[2 * c + 1], v.z, v.w);
        v.x *= dA; v.y *= dA; v.z *= dA; v.w *= dA;
        uA[c] = v;
    }
    if (two) {
        float dB = g_dinv[n1];
        float4* uB = reinterpret_cast<float4*>(g_u + (size_t)n1 * N_CLASSES);
#pragma unroll
        for (int c = 0; c < C4; c++) {
            float4 v;
            unpack2(accB[2 * c],     v.x, v.y);
            unpack2(accB[2 * c + 1], v.z, v.w);
            v.x *= dB; v.y *= dB; v.z *= dB; v.w *= dB;
            uB[c] = v;
        }
    }
}

// ───────────────── pull hop: t[n] = u[n] + Σ_{e∈row(n)} u[col[e]] ─────────
// 10 threads per node (one float4 chunk each); 320-thread blocks = 32 nodes.
__global__ void __launch_bounds__(320) k_pull() {
    int tid = threadIdx.x;
    int n = blockIdx.x * 32 + tid / 10;
    int j = tid % 10;
    if (n >= N_NODES) return;

    const float4* u4 = reinterpret_cast<const float4*>(g_u);
    int r0 = g_rowptr[n];
    int r1 = g_rowptr[n + 1];

    float4 a0 = u4[n * C4 + j];  // self-loop term
    float4 a1 = make_float4(0.f, 0.f, 0.f, 0.f);
    float4 a2 = make_float4(0.f, 0.f, 0.f, 0.f);
    float4 a3 = make_float4(0.f, 0.f, 0.f, 0.f);

    int e = r0;
    for (; e + 4 <= r1; e += 4) {
        int c0 = g_col[e], c1 = g_col[e + 1], c2 = g_col[e + 2], c3 = g_col[e + 3];
        float4 v0 = u4[c0 * C4 + j];
        float4 v1 = u4[c1 * C4 + j];
        float4 v2 = u4[c2 * C4 + j];
        float4 v3 = u4[c3 * C4 + j];
        a0.x += v0.x; a0.y += v0.y; a0.z += v0.z; a0.w += v0.w;
        a1.x += v1.x; a1.y += v1.y; a1.z += v1.z; a1.w += v1.w;
        a2.x += v2.x; a2.y += v2.y; a2.z += v2.z; a2.w += v2.w;
        a3.x += v3.x; a3.y += v3.y; a3.z += v3.z; a3.w += v3.w;
    }
    for (; e < r1; e++) {
        int c = g_col[e];
        float4 v = u4[c * C4 + j];
        a0.x += v.x; a0.y += v.y; a0.z += v.z; a0.w += v.w;
    }
    float4 r;
    r.x = (a0.x + a1.x) + (a2.x + a3.x);
    r.y = (a0.y + a1.y) + (a2.y + a3.y);
    r.z = (a0.z + a1.z) + (a2.z + a3.z);
    r.w = (a0.w + a1.w) + (a2.w + a3.w);
    reinterpret_cast<float4*>(g_t)[n * C4 + j] = r;
}

// Between hops: u = dinv^2 * t
__global__ void k_mid() {
    int i = blockIdx.x * blockDim.x + threadIdx.x;
    if (i >= N_NODES * C4) return;
    int n = i / C4;
    float di = g_dinv[n];
    float s = di * di;
    float4 v = reinterpret_cast<const float4*>(g_t)[i];
    v.x *= s; v.y *= s; v.z *= s; v.w *= s;
    reinterpret_cast<float4*>(g_u)[i] = v;
}

// out = log_softmax(dinv*t + b)
__global__ void k_logsoftmax(const float* __restrict__ bias, float* __restrict__ out) {
    __shared__ float bs[N_CLASSES];
    if (threadIdx.x < N_CLASSES) bs[threadIdx.x] = bias[threadIdx.x];
    __syncthreads();
    int n = blockIdx.x * blockDim.x + threadIdx.x;
    if (n >= N_NODES) return;

    float di = g_dinv[n];
    float v[N_CLASSES];
    const float4* in = reinterpret_cast<const float4*>(g_t + (size_t)n * N_CLASSES);
#pragma unroll
    for (int j = 0; j < C4; j++) {
        float4 tv = in[j];
        v[4 * j + 0] = tv.x * di + bs[4 * j + 0];
        v[4 * j + 1] = tv.y * di + bs[4 * j + 1];
        v[4 * j + 2] = tv.z * di + bs[4 * j + 2];
        v[4 * j + 3] = tv.w * di + bs[4 * j + 3];
    }
    float m = v[0];
#pragma unroll
    for (int c = 1; c < N_CLASSES; c++) m = fmaxf(m, v[c]);
    float sum = 0.f;
#pragma unroll
    for (int c = 0; c < N_CLASSES; c++) sum += __expf(v[c] - m);
    float lse = m + __logf(sum);

    float4* o = reinterpret_cast<float4*>(out + (size_t)n * N_CLASSES);
#pragma unroll
    for (int j = 0; j < C4; j++) {
        float4 tv;
        tv.x = v[4 * j + 0] - lse;
        tv.y = v[4 * j + 1] - lse;
        tv.z = v[4 * j + 2] - lse;
        tv.w = v[4 * j + 3] - lse;
        o[j] = tv;
    }
}

extern "C" void kernel_launch(void* const* d_in, const int* in_sizes, int n_in,
                              void* d_out, int out_size) {
    const float* x  = (const float*)d_in[0];  // [100000,128]
    const float* W  = (const float*)d_in[1];  // [128,40]
    const float* b  = (const float*)d_in[2];  // [40]
    const int*   ei = (const int*)d_in[3];    // [2,1600000]
    const int* src = ei;
    const int* dst = ei + N_EDGES;
    float* out = (float*)d_out;

    const int TB = 256;
    const int gN  = (N_NODES + TB - 1) / TB;
    const int gE2 = (N_EDGES / 2 + TB - 1) / TB;
    const int gI  = (N_NODES * C4 + TB - 1) / TB;
    const int gMM = (N_NODES + 511) / 512;
    const int gP  = (N_NODES + 31) / 32;

    // degree + normalization
    k_zero_deg<<<gN, TB>>>();
    k_deg<<<gE2, TB>>>(dst);
    k_dinv<<<gN, TB>>>();

    // CSR build (by dst)
    k_scan1<<<NB_SCAN, 256>>>();
    k_scan2<<<1, 128>>>();
    k_scan3<<<gN, TB>>>();
    k_fill<<<gE2, TB>>>(src, dst);

    // Project to class space first: (A^K x) W == A^K (x W)
    k_matmul<<<gMM, TB>>>(x, W);

    // Two pull hops (no atomics)
    k_pull<<<gP, 320>>>();   // hop 1: t = u_self + gather
    k_mid<<<gI, TB>>>();     // u = dinv^2 * t
    k_pull<<<gP, 320>>>();   // hop 2

    k_logsoftmax<<<gN, TB>>>(b, out);
}

// round 12
// speedup vs baseline: 2.0886x; 1.0748x over previous
#include <cuda_runtime.h>

#define N_NODES   100000
#define N_FEAT    128
#define N_CLASSES 40
#define N_EDGES   1600000
#define C4        10   // float4 chunks per 40-float row
#define SCAN_CHUNK 1024
#define NB_SCAN   ((N_NODES + SCAN_CHUNK - 1) / SCAN_CHUNK)  // 98

// Scratch (static device globals — no allocation anywhere)
__device__ float g_u[N_NODES * N_CLASSES];   // payload ping
__device__ float g_t[N_NODES * N_CLASSES];   // payload pong
__device__ float g_dinv[N_NODES];
__device__ int   g_deg[N_NODES];
__device__ int   g_rowptr[N_NODES + 1];
__device__ int   g_cursor[N_NODES];
__device__ int   g_col[N_EDGES];
__device__ int   g_bsum[NB_SCAN];
__device__ int   g_boff[NB_SCAN];

typedef unsigned long long u64;

__device__ __forceinline__ u64 pack2(float a, float b) {
    u64 p; asm("mov.b64 %0, {%1, %2};" : "=l"(p) : "f"(a), "f"(b)); return p;
}
__device__ __forceinline__ void unpack2(u64 p, float& a, float& b) {
    asm("mov.b64 {%0, %1}, %2;" : "=f"(a), "=f"(b) : "l"(p));
}
#define FMA_F32X2(d, a, b, c) \
    asm("fma.rn.f32x2 %0, %1, %2, %3;" : "=l"(d) : "l"(a), "l"(b), "l"(c))

// ───────────────────────── degree ─────────────────────────
__global__ void k_zero_deg() {
    int i = blockIdx.x * blockDim.x + threadIdx.x;
    if (i < N_NODES) g_deg[i] = 0;
}

// 4 edges per thread via int4 index loads
__global__ void k_deg(const int* __restrict__ dst) {
    int t = blockIdx.x * blockDim.x + threadIdx.x;
    if (t < N_EDGES / 4) {
        int4 d4 = reinterpret_cast<const int4*>(dst)[t];
        atomicAdd(&g_deg[d4.x], 1);
        atomicAdd(&g_deg[d4.y], 1);
        atomicAdd(&g_deg[d4.z], 1);
        atomicAdd(&g_deg[d4.w], 1);
    }
}

// ─────────────── CSR build: scan (dinv fused) + fill ──────────────────────
__global__ void k_scan1() {
    __shared__ int sh[256];
    int tid = threadIdx.x;
    int base = blockIdx.x * SCAN_CHUNK + tid * 4;
    int v[4]; int s = 0;
#pragma unroll
    for (int i = 0; i < 4; i++) {
        int idx = base + i;
        v[i] = (idx < N_NODES) ? g_deg[idx] : 0;
        if (idx < N_NODES) g_dinv[idx] = rsqrtf((float)(v[i] + 1));  // +1 self loop
        s += v[i];
    }
    int val = s;
    sh[tid] = val; __syncthreads();
#pragma unroll
    for (int off = 1; off < 256; off <<= 1) {
        int add = (tid >= off) ? sh[tid - off] : 0;
        __syncthreads();
        val += add; sh[tid] = val;
        __syncthreads();
    }
    if (tid == 255) g_bsum[blockIdx.x] = val;
    int run = val - s;
#pragma unroll
    for (int i = 0; i < 4; i++) {
        int idx = base + i;
        if (idx < N_NODES) g_rowptr[idx] = run;
        run += v[i];
    }
}

__global__ void k_scan2() {
    __shared__ int sh[128];
    int tid = threadIdx.x;
    int v = (tid < NB_SCAN) ? g_bsum[tid] : 0;
    int val = v;
    sh[tid] = val; __syncthreads();
#pragma unroll
    for (int off = 1; off < 128; off <<= 1) {
        int add = (tid >= off) ? sh[tid - off] : 0;
        __syncthreads();
        val += add; sh[tid] = val;
        __syncthreads();
    }
    if (tid < NB_SCAN) g_boff[tid] = val - v;
}

__global__ void k_scan3() {
    int i = blockIdx.x * blockDim.x + threadIdx.x;
    if (i < N_NODES) {
        int r = g_rowptr[i] + g_boff[i / SCAN_CHUNK];
        g_rowptr[i] = r;
        g_cursor[i] = r;
    }
    if (i == 0) g_rowptr[N_NODES] = N_EDGES;
}

__global__ void k_fill(const int* __restrict__ src, const int* __restrict__ dst) {
    int t = blockIdx.x * blockDim.x + threadIdx.x;
    if (t >= N_EDGES / 4) return;
    int4 s4 = reinterpret_cast<const int4*>(src)[t];
    int4 d4 = reinterpret_cast<const int4*>(dst)[t];
    int p0 = atomicAdd(&g_cursor[d4.x], 1); g_col[p0] = s4.x;
    int p1 = atomicAdd(&g_cursor[d4.y], 1); g_col[p1] = s4.y;
    int p2 = atomicAdd(&g_cursor[d4.z], 1); g_col[p2] = s4.z;
    int p3 = atomicAdd(&g_cursor[d4.w], 1); g_col[p3] = s4.w;
}

// ──────────── u = dinv ⊙ (x@W). 4 nodes × 10 classes per thread ────────────
__global__ void __launch_bounds__(256) k_matmul(const float* __restrict__ x,
                                                const float* __restrict__ W) {
    __shared__ u64 Ws[N_FEAT * 20];  // [k][pair]: (W[k][2p], W[k][2p+1]) packed
    for (int i = threadIdx.x; i < N_FEAT * 20; i += blockDim.x)
        Ws[i] = reinterpret_cast<const u64*>(W)[i];  // float2 bits
    __syncthreads();

    int tid = threadIdx.x;
    int g  = tid & 3;         // class group: classes [10g, 10g+10)
    int ng = tid >> 2;        // node group within block (0..63)
    int n0 = blockIdx.x * 256 + ng * 4;
    if (n0 >= N_NODES) return;

    u64 acc[4][5];
#pragma unroll
    for (int i = 0; i < 4; i++)
#pragma unroll
        for (int p = 0; p < 5; p++) acc[i][p] = 0ull;

    const float4* xr[4];
#pragma unroll
    for (int i = 0; i < 4; i++) {
        int nr = n0 + i; if (nr >= N_NODES) nr = N_NODES - 1;
        xr[i] = reinterpret_cast<const float4*>(x + (size_t)nr * N_FEAT);
    }

    const u64* wg = Ws + 5 * g;
#pragma unroll 2
    for (int k4 = 0; k4 < N_FEAT / 4; k4++) {
        float4 xv[4];
#pragma unroll
        for (int i = 0; i < 4; i++) xv[i] = xr[i][k4];
#pragma unroll
        for (int j = 0; j < 4; j++) {
            int k = k4 * 4 + j;
            const u64* wk = wg + k * 20;
            u64 w0 = wk[0], w1 = wk[1], w2 = wk[2], w3 = wk[3], w4 = wk[4];
#pragma unroll
            for (int i = 0; i < 4; i++) {
                float f = (j == 0) ? xv[i].x : (j == 1) ? xv[i].y
                        : (j == 2) ? xv[i].z : xv[i].w;
                u64 f2 = pack2(f, f);
                FMA_F32X2(acc[i][0], f2, w0, acc[i][0]);
                FMA_F32X2(acc[i][1], f2, w1, acc[i][1]);
                FMA_F32X2(acc[i][2], f2, w2, acc[i][2]);
                FMA_F32X2(acc[i][3], f2, w3, acc[i][3]);
                FMA_F32X2(acc[i][4], f2, w4, acc[i][4]);
            }
        }
    }

#pragma unroll
    for (int i = 0; i < 4; i++) {
        int n = n0 + i;
        if (n >= N_NODES) break;
        float di = g_dinv[n];
        float2* row = reinterpret_cast<float2*>(g_u + (size_t)n * N_CLASSES + 10 * g);
#pragma unroll
        for (int p = 0; p < 5; p++) {
            float lo, hi;
            unpack2(acc[i][p], lo, hi);
            row[p] = make_float2(lo * di, hi * di);
        }
    }
}

// ──────── pull hop: out[n] = scale · (u[n] + Σ_{e∈row(n)} u[col[e]]) ───────
// 10 threads per node (one float4 each); 320-thread blocks = 32 nodes.
// dir == 0: read g_u, write g_t ; dir == 1: read g_t, write g_u.
// Buffer addresses taken INSIDE device code (host-side __device__ symbol
// addresses are invalid — that was the R4/R6/R9 bug).
// scaled != 0 → scale = dinv[n]^2 (prepares next hop's source; replaces k_mid).
__global__ void __launch_bounds__(320) k_pull(int dir, int scaled) {
    const float4* uin  = dir ? reinterpret_cast<const float4*>(g_t)
                             : reinterpret_cast<const float4*>(g_u);
    float4*       uout = dir ? reinterpret_cast<float4*>(g_u)
                             : reinterpret_cast<float4*>(g_t);
    int tid = threadIdx.x;
    int n = blockIdx.x * 32 + tid / 10;
    int j = tid % 10;
    if (n >= N_NODES) return;

    int r0 = g_rowptr[n];
    int r1 = g_rowptr[n + 1];

    float4 a0 = uin[n * C4 + j];  // self-loop term
    float4 a1 = make_float4(0.f, 0.f, 0.f, 0.f);
    float4 a2 = make_float4(0.f, 0.f, 0.f, 0.f);
    float4 a3 = make_float4(0.f, 0.f, 0.f, 0.f);

    int e = r0;
    for (; e + 4 <= r1; e += 4) {
        int c0 = g_col[e], c1 = g_col[e + 1], c2 = g_col[e + 2], c3 = g_col[e + 3];
        float4 v0 = uin[c0 * C4 + j];
        float4 v1 = uin[c1 * C4 + j];
        float4 v2 = uin[c2 * C4 + j];
        float4 v3 = uin[c3 * C4 + j];
        a0.x += v0.x; a0.y += v0.y; a0.z += v0.z; a0.w += v0.w;
        a1.x += v1.x; a1.y += v1.y; a1.z += v1.z; a1.w += v1.w;
        a2.x += v2.x; a2.y += v2.y; a2.z += v2.z; a2.w += v2.w;
        a3.x += v3.x; a3.y += v3.y; a3.z += v3.z; a3.w += v3.w;
    }
    for (; e < r1; e++) {
        int c = g_col[e];
        float4 v = uin[c * C4 + j];
        a0.x += v.x; a0.y += v.y; a0.z += v.z; a0.w += v.w;
    }
    float sc = 1.f;
    if (scaled) { float di = g_dinv[n]; sc = di * di; }
    float4 r;
    r.x = ((a0.x + a1.x) + (a2.x + a3.x)) * sc;
    r.y = ((a0.y + a1.y) + (a2.y + a3.y)) * sc;
    r.z = ((a0.z + a1.z) + (a2.z + a3.z)) * sc;
    r.w = ((a0.w + a1.w) + (a2.w + a3.w)) * sc;
    uout[n * C4 + j] = r;
}

// out = log_softmax(dinv*u + b)
__global__ void k_logsoftmax(const float* __restrict__ bias, float* __restrict__ out) {
    __shared__ float bs[N_CLASSES];
    if (threadIdx.x < N_CLASSES) bs[threadIdx.x] = bias[threadIdx.x];
    __syncthreads();
    int n = blockIdx.x * blockDim.x + threadIdx.x;
    if (n >= N_NODES) return;

    float di = g_dinv[n];
    float v[N_CLASSES];
    const float4* in = reinterpret_cast<const float4*>(g_u + (size_t)n * N_CLASSES);
#pragma unroll
    for (int j = 0; j < C4; j++) {
        float4 tv = in[j];
        v[4 * j + 0] = tv.x * di + bs[4 * j + 0];
        v[4 * j + 1] = tv.y * di + bs[4 * j + 1];
        v[4 * j + 2] = tv.z * di + bs[4 * j + 2];
        v[4 * j + 3] = tv.w * di + bs[4 * j + 3];
    }
    float m = v[0];
#pragma unroll
    for (int c = 1; c < N_CLASSES; c++) m = fmaxf(m, v[c]);
    float sum = 0.f;
#pragma unroll
    for (int c = 0; c < N_CLASSES; c++) sum += __expf(v[c] - m);
    float lse = m + __logf(sum);

    float4* o = reinterpret_cast<float4*>(out + (size_t)n * N_CLASSES);
#pragma unroll
    for (int j = 0; j < C4; j++) {
        float4 tv;
        tv.x = v[4 * j + 0] - lse;
        tv.y = v[4 * j + 1] - lse;
        tv.z = v[4 * j + 2] - lse;
        tv.w = v[4 * j + 3] - lse;
        o[j] = tv;
    }
}

extern "C" void kernel_launch(void* const* d_in, const int* in_sizes, int n_in,
                              void* d_out, int out_size) {
    const float* x  = (const float*)d_in[0];  // [100000,128]
    const float* W  = (const float*)d_in[1];  // [128,40]
    const float* b  = (const float*)d_in[2];  // [40]
    const int*   ei = (const int*)d_in[3];    // [2,1600000]
    const int* src = ei;
    const int* dst = ei + N_EDGES;
    float* out = (float*)d_out;

    const int TB = 256;
    const int gN  = (N_NODES + TB - 1) / TB;
    const int gE4 = (N_EDGES / 4 + TB - 1) / TB;
    const int gMM = (N_NODES + 255) / 256;
    const int gP  = (N_NODES + 31) / 32;

    k_zero_deg<<<gN, TB>>>();
    k_deg<<<gE4, TB>>>(dst);

    // CSR build (by dst); dinv fused into scan1
    k_scan1<<<NB_SCAN, 256>>>();
    k_scan2<<<1, 128>>>();
    k_scan3<<<gN, TB>>>();
    k_fill<<<gE4, TB>>>(src, dst);

    // Project to class space first: (A^K x) W == A^K (x W)
    k_matmul<<<gMM, TB>>>(x, W);

    // Two pull hops (no atomics); hop1 epilogue applies dinv^2 (fused k_mid)
    k_pull<<<gP, 320>>>(0, 1);   // g_u -> g_t, scaled by dinv^2
    k_pull<<<gP, 320>>>(1, 0);   // g_t -> g_u

    k_logsoftmax<<<gN, TB>>>(b, out);
}

// round 13
// speedup vs baseline: 2.2509x; 1.0777x over previous
#include <cuda_runtime.h>

#define N_NODES   100000
#define N_FEAT    128
#define N_CLASSES 40
#define N_EDGES   1600000
#define C4        10   // float4 chunks per 40-float row
#define SCAN_CHUNK 1024
#define NB_SCAN   ((N_NODES + SCAN_CHUNK - 1) / SCAN_CHUNK)  // 98

// Scratch (static device globals — no allocation anywhere).
// g_deg starts zeroed (module init) and is re-zeroed by k_scan3 every call,
// so every invocation performs identical work on identical state.
__device__ float g_u[N_NODES * N_CLASSES];   // payload ping
__device__ float g_t[N_NODES * N_CLASSES];   // payload pong
__device__ float g_dinv[N_NODES];
__device__ int   g_deg[N_NODES];
__device__ int   g_rowptr[N_NODES + 1];
__device__ int   g_cursor[N_NODES];
__device__ int   g_col[N_EDGES];
__device__ int   g_bsum[NB_SCAN];

typedef unsigned long long u64;

__device__ __forceinline__ u64 pack2(float a, float b) {
    u64 p; asm("mov.b64 %0, {%1, %2};" : "=l"(p) : "f"(a), "f"(b)); return p;
}
__device__ __forceinline__ void unpack2(u64 p, float& a, float& b) {
    asm("mov.b64 {%0, %1}, %2;" : "=f"(a), "=f"(b) : "l"(p));
}
#define FMA_F32X2(d, a, b, c) \
    asm("fma.rn.f32x2 %0, %1, %2, %3;" : "=l"(d) : "l"(a), "l"(b), "l"(c))

// ───────────────────────── degree (deg assumed 0 at entry) ─────────────────
__global__ void k_deg(const int* __restrict__ dst) {
    int t = blockIdx.x * blockDim.x + threadIdx.x;
    if (t < N_EDGES / 4) {
        int4 d4 = reinterpret_cast<const int4*>(dst)[t];
        atomicAdd(&g_deg[d4.x], 1);
        atomicAdd(&g_deg[d4.y], 1);
        atomicAdd(&g_deg[d4.z], 1);
        atomicAdd(&g_deg[d4.w], 1);
    }
}

// ─────────────── CSR build: scan1 (dinv fused) ─────────────────────────────
__global__ void k_scan1() {
    __shared__ int sh[256];
    int tid = threadIdx.x;
    int base = blockIdx.x * SCAN_CHUNK + tid * 4;
    int v[4]; int s = 0;
#pragma unroll
    for (int i = 0; i < 4; i++) {
        int idx = base + i;
        v[i] = (idx < N_NODES) ? g_deg[idx] : 0;
        if (idx < N_NODES) g_dinv[idx] = rsqrtf((float)(v[i] + 1));  // +1 self loop
        s += v[i];
    }
    int val = s;
    sh[tid] = val; __syncthreads();
#pragma unroll
    for (int off = 1; off < 256; off <<= 1) {
        int add = (tid >= off) ? sh[tid - off] : 0;
        __syncthreads();
        val += add; sh[tid] = val;
        __syncthreads();
    }
    if (tid == 255) g_bsum[blockIdx.x] = val;
    int run = val - s;
#pragma unroll
    for (int i = 0; i < 4; i++) {
        int idx = base + i;
        if (idx < N_NODES) g_rowptr[idx] = run;
        run += v[i];
    }
}

// scan3: per-block redundant scan of the 98 block sums (replaces k_scan2),
// finalize rowptr, init cursor, and re-zero g_deg for the next invocation.
__global__ void k_scan3() {
    __shared__ int sh[128];
    int tid = threadIdx.x;
    int val = 0;
    if (tid < 128) {
        val = (tid < NB_SCAN) ? g_bsum[tid] : 0;
        sh[tid] = val;
    }
    __syncthreads();
#pragma unroll
    for (int off = 1; off < 128; off <<= 1) {
        int add = (tid < 128 && tid >= off) ? sh[tid - off] : 0;
        __syncthreads();
        if (tid < 128) { val += add; sh[tid] = val; }
        __syncthreads();
    }
    // sh[c] = inclusive prefix of bsum
    int i = blockIdx.x * blockDim.x + tid;
    if (i < N_NODES) {
        int c = i / SCAN_CHUNK;
        int boff = (c == 0) ? 0 : sh[c - 1];
        int r = g_rowptr[i] + boff;
        g_rowptr[i] = r;
        g_cursor[i] = r;
        g_deg[i] = 0;   // restore for next call
    }
    if (i == 0) g_rowptr[N_NODES] = N_EDGES;
}

__global__ void k_fill(const int* __restrict__ src, const int* __restrict__ dst) {
    int t = blockIdx.x * blockDim.x + threadIdx.x;
    if (t >= N_EDGES / 4) return;
    int4 s4 = reinterpret_cast<const int4*>(src)[t];
    int4 d4 = reinterpret_cast<const int4*>(dst)[t];
    int p0 = atomicAdd(&g_cursor[d4.x], 1); g_col[p0] = s4.x;
    int p1 = atomicAdd(&g_cursor[d4.y], 1); g_col[p1] = s4.y;
    int p2 = atomicAdd(&g_cursor[d4.z], 1); g_col[p2] = s4.z;
    int p3 = atomicAdd(&g_cursor[d4.w], 1); g_col[p3] = s4.w;
}

// ──────────── u = dinv ⊙ (x@W). 4 nodes × 10 classes per thread ────────────
__global__ void __launch_bounds__(256) k_matmul(const float* __restrict__ x,
                                                const float* __restrict__ W) {
    __shared__ u64 Ws[N_FEAT * 20];  // [k][pair]: (W[k][2p], W[k][2p+1]) packed
    for (int i = threadIdx.x; i < N_FEAT * 20; i += blockDim.x)
        Ws[i] = reinterpret_cast<const u64*>(W)[i];  // float2 bits
    __syncthreads();

    int tid = threadIdx.x;
    int g  = tid & 3;         // class group: classes [10g, 10g+10)
    int ng = tid >> 2;        // node group within block (0..63)
    int n0 = blockIdx.x * 256 + ng * 4;
    if (n0 >= N_NODES) return;

    u64 acc[4][5];
#pragma unroll
    for (int i = 0; i < 4; i++)
#pragma unroll
        for (int p = 0; p < 5; p++) acc[i][p] = 0ull;

    const float4* xr[4];
#pragma unroll
    for (int i = 0; i < 4; i++) {
        int nr = n0 + i; if (nr >= N_NODES) nr = N_NODES - 1;
        xr[i] = reinterpret_cast<const float4*>(x + (size_t)nr * N_FEAT);
    }

    const u64* wg = Ws + 5 * g;
#pragma unroll 2
    for (int k4 = 0; k4 < N_FEAT / 4; k4++) {
        float4 xv[4];
#pragma unroll
        for (int i = 0; i < 4; i++) xv[i] = xr[i][k4];
#pragma unroll
        for (int j = 0; j < 4; j++) {
            int k = k4 * 4 + j;
            const u64* wk = wg + k * 20;
            u64 w0 = wk[0], w1 = wk[1], w2 = wk[2], w3 = wk[3], w4 = wk[4];
#pragma unroll
            for (int i = 0; i < 4; i++) {
                float f = (j == 0) ? xv[i].x : (j == 1) ? xv[i].y
                        : (j == 2) ? xv[i].z : xv[i].w;
                u64 f2 = pack2(f, f);
                FMA_F32X2(acc[i][0], f2, w0, acc[i][0]);
                FMA_F32X2(acc[i][1], f2, w1, acc[i][1]);
                FMA_F32X2(acc[i][2], f2, w2, acc[i][2]);
                FMA_F32X2(acc[i][3], f2, w3, acc[i][3]);
                FMA_F32X2(acc[i][4], f2, w4, acc[i][4]);
            }
        }
    }

#pragma unroll
    for (int i = 0; i < 4; i++) {
        int n = n0 + i;
        if (n >= N_NODES) break;
        float di = g_dinv[n];
        float2* row = reinterpret_cast<float2*>(g_u + (size_t)n * N_CLASSES + 10 * g);
#pragma unroll
        for (int p = 0; p < 5; p++) {
            float lo, hi;
            unpack2(acc[i][p], lo, hi);
            row[p] = make_float2(lo * di, hi * di);
        }
    }
}

// ──────── hop 1: g_t[n] = dinv^2 · (g_u[n] + Σ_{e∈row(n)} g_u[col[e]]) ─────
// 10 threads/node (one float4 each); 320-thread blocks = 32 nodes; 3125 blocks
// exactly cover 100000 nodes (no partial blocks).
__global__ void __launch_bounds__(320) k_pull1() {
    const float4* uin = reinterpret_cast<const float4*>(g_u);
    int tid = threadIdx.x;
    int n = blockIdx.x * 32 + tid / 10;
    int j = tid % 10;

    int r0 = g_rowptr[n];
    int r1 = g_rowptr[n + 1];

    float4 a0 = uin[n * C4 + j];  // self-loop term
    float4 a1 = make_float4(0.f, 0.f, 0.f, 0.f);
    float4 a2 = make_float4(0.f, 0.f, 0.f, 0.f);
    float4 a3 = make_float4(0.f, 0.f, 0.f, 0.f);

    int e = r0;
    for (; e + 4 <= r1; e += 4) {
        int c0 = g_col[e], c1 = g_col[e + 1], c2 = g_col[e + 2], c3 = g_col[e + 3];
        float4 v0 = uin[c0 * C4 + j];
        float4 v1 = uin[c1 * C4 + j];
        float4 v2 = uin[c2 * C4 + j];
        float4 v3 = uin[c3 * C4 + j];
        a0.x += v0.x; a0.y += v0.y; a0.z += v0.z; a0.w += v0.w;
        a1.x += v1.x; a1.y += v1.y; a1.z += v1.z; a1.w += v1.w;
        a2.x += v2.x; a2.y += v2.y; a2.z += v2.z; a2.w += v2.w;
        a3.x += v3.x; a3.y += v3.y; a3.z += v3.z; a3.w += v3.w;
    }
    for (; e < r1; e++) {
        int c = g_col[e];
        float4 v = uin[c * C4 + j];
        a0.x += v.x; a0.y += v.y; a0.z += v.z; a0.w += v.w;
    }
    float di = g_dinv[n];
    float sc = di * di;
    float4 r;
    r.x = ((a0.x + a1.x) + (a2.x + a3.x)) * sc;
    r.y = ((a0.y + a1.y) + (a2.y + a3.y)) * sc;
    r.z = ((a0.z + a1.z) + (a2.z + a3.z)) * sc;
    r.w = ((a0.w + a1.w) + (a2.w + a3.w)) * sc;
    reinterpret_cast<float4*>(g_t)[n * C4 + j] = r;
}

// ──── hop 2 + log-softmax fused: out[n] = lsm(dinv·(t_self+gather) + b) ────
__global__ void __launch_bounds__(320) k_pull2_lsm(const float* __restrict__ bias,
                                                   float* __restrict__ out) {
    __shared__ float bs[N_CLASSES];
    __shared__ float red[2][320];
    int tid = threadIdx.x;
    if (tid < N_CLASSES) bs[tid] = bias[tid];
    __syncthreads();

    const float4* uin = reinterpret_cast<const float4*>(g_t);
    int n = blockIdx.x * 32 + tid / 10;
    int j = tid % 10;

    int r0 = g_rowptr[n];
    int r1 = g_rowptr[n + 1];

    float4 a0 = uin[n * C4 + j];  // self-loop term
    float4 a1 = make_float4(0.f, 0.f, 0.f, 0.f);
    float4 a2 = make_float4(0.f, 0.f, 0.f, 0.f);
    float4 a3 = make_float4(0.f, 0.f, 0.f, 0.f);

    int e = r0;
    for (; e + 4 <= r1; e += 4) {
        int c0 = g_col[e], c1 = g_col[e + 1], c2 = g_col[e + 2], c3 = g_col[e + 3];
        float4 v0 = uin[c0 * C4 + j];
        float4 v1 = uin[c1 * C4 + j];
        float4 v2 = uin[c2 * C4 + j];
        float4 v3 = uin[c3 * C4 + j];
        a0.x += v0.x; a0.y += v0.y; a0.z += v0.z; a0.w += v0.w;
        a1.x += v1.x; a1.y += v1.y; a1.z += v1.z; a1.w += v1.w;
        a2.x += v2.x; a2.y += v2.y; a2.z += v2.z; a2.w += v2.w;
        a3.x += v3.x; a3.y += v3.y; a3.z += v3.z; a3.w += v3.w;
    }
    for (; e < r1; e++) {
        int c = g_col[e];
        float4 v = uin[c * C4 + j];
        a0.x += v.x; a0.y += v.y; a0.z += v.z; a0.w += v.w;
    }

    float di = g_dinv[n];
    float4 v;
    v.x = ((a0.x + a1.x) + (a2.x + a3.x)) * di + bs[4 * j + 0];
    v.y = ((a0.y + a1.y) + (a2.y + a3.y)) * di + bs[4 * j + 1];
    v.z = ((a0.z + a1.z) + (a2.z + a3.z)) * di + bs[4 * j + 2];
    v.w = ((a0.w + a1.w) + (a2.w + a3.w)) * di + bs[4 * j + 3];

    // log-softmax across the node's 10 threads via smem
    int base = (tid / 10) * 10;
    red[0][tid] = fmaxf(fmaxf(v.x, v.y), fmaxf(v.z, v.w));
    __syncthreads();
    float m = red[0][base];
#pragma unroll
    for (int k = 1; k < 10; k++) m = fmaxf(m, red[0][base + k]);
    red[1][tid] = __expf(v.x - m) + __expf(v.y - m) + __expf(v.z - m) + __expf(v.w - m);
    __syncthreads();
    float sum = 0.f;
#pragma unroll
    for (int k = 0; k < 10; k++) sum += red[1][base + k];
    float lse = m + __logf(sum);

    float4 o;
    o.x = v.x - lse; o.y = v.y - lse; o.z = v.z - lse; o.w = v.w - lse;
    reinterpret_cast<float4*>(out)[n * C4 + j] = o;
}

extern "C" void kernel_launch(void* const* d_in, const int* in_sizes, int n_in,
                              void* d_out, int out_size) {
    const float* x  = (const float*)d_in[0];  // [100000,128]
    const float* W  = (const float*)d_in[1];  // [128,40]
    const float* b  = (const float*)d_in[2];  // [40]
    const int*   ei = (const int*)d_in[3];    // [2,1600000]
    const int* src = ei;
    const int* dst = ei + N_EDGES;
    float* out = (float*)d_out;

    const int TB = 256;
    const int gN  = (N_NODES + TB - 1) / TB;
    const int gE4 = (N_EDGES / 4 + TB - 1) / TB;
    const int gMM = (N_NODES + 255) / 256;
    const int gP  = N_NODES / 32;   // 3125, exact

    k_deg<<<gE4, TB>>>(dst);        // g_deg was zeroed by previous call / init
    k_scan1<<<NB_SCAN, 256>>>();    // rowptr partials + bsum + dinv
    k_scan3<<<gN, TB>>>();          // finalize rowptr, cursor, re-zero deg
    k_fill<<<gE4, TB>>>(src, dst);  // CSR col

    // Project to class space first: (A^K x) W == A^K (x W)
    k_matmul<<<gMM, TB>>>(x, W);

    k_pull1<<<gP, 320>>>();             // g_u -> g_t, ×dinv^2
    k_pull2_lsm<<<gP, 320>>>(b, out);   // g_t -> out, fused log-softmax
}

// round 14
// speedup vs baseline: 2.4376x; 1.0829x over previous
#include <cuda_runtime.h>

#define N_NODES   100000
#define N_FEAT    128
#define N_CLASSES 40
#define N_EDGES   1600000
#define C4        10   // float4 chunks per 40-float row
#define SCAN_CHUNK 1024
#define NB_SCAN   ((N_NODES + SCAN_CHUNK - 1) / SCAN_CHUNK)  // 98

// Scratch (static device globals — no allocation anywhere).
// g_deg starts zeroed (module init) and is re-zeroed by k_pull1 every call,
// so every invocation performs identical work on identical state.
__device__ float g_u[N_NODES * N_CLASSES];   // payload ping
__device__ float g_t[N_NODES * N_CLASSES];   // payload pong
__device__ float g_dinv[N_NODES];
__device__ int   g_deg[N_NODES];
__device__ int   g_rowptr[N_NODES + 1];
__device__ int   g_cursor[N_NODES];
__device__ int   g_col[N_EDGES];
__device__ int   g_bsum[NB_SCAN];

typedef unsigned long long u64;

__device__ __forceinline__ u64 pack2(float a, float b) {
    u64 p; asm("mov.b64 %0, {%1, %2};" : "=l"(p) : "f"(a), "f"(b)); return p;
}
__device__ __forceinline__ void unpack2(u64 p, float& a, float& b) {
    asm("mov.b64 {%0, %1}, %2;" : "=f"(a), "=f"(b) : "l"(p));
}
#define FMA_F32X2(d, a, b, c) \
    asm("fma.rn.f32x2 %0, %1, %2, %3;" : "=l"(d) : "l"(a), "l"(b), "l"(c))

// ─────────── degree (deg assumed 0 at entry); 8 edges/thread ───────────────
__global__ void k_deg(const int* __restrict__ dst) {
    int t = blockIdx.x * blockDim.x + threadIdx.x;
    if (t < N_EDGES / 8) {
        int4 a = reinterpret_cast<const int4*>(dst)[2 * t];
        int4 b = reinterpret_cast<const int4*>(dst)[2 * t + 1];
        atomicAdd(&g_deg[a.x], 1); atomicAdd(&g_deg[a.y], 1);
        atomicAdd(&g_deg[a.z], 1); atomicAdd(&g_deg[a.w], 1);
        atomicAdd(&g_deg[b.x], 1); atomicAdd(&g_deg[b.y], 1);
        atomicAdd(&g_deg[b.z], 1); atomicAdd(&g_deg[b.w], 1);
    }
}

// ─────────────── CSR build: scan1 (dinv fused) ─────────────────────────────
__global__ void k_scan1() {
    __shared__ int sh[256];
    int tid = threadIdx.x;
    int base = blockIdx.x * SCAN_CHUNK + tid * 4;
    int v[4]; int s = 0;
#pragma unroll
    for (int i = 0; i < 4; i++) {
        int idx = base + i;
        v[i] = (idx < N_NODES) ? g_deg[idx] : 0;
        if (idx < N_NODES) g_dinv[idx] = rsqrtf((float)(v[i] + 1));  // +1 self loop
        s += v[i];
    }
    int val = s;
    sh[tid] = val; __syncthreads();
#pragma unroll
    for (int off = 1; off < 256; off <<= 1) {
        int add = (tid >= off) ? sh[tid - off] : 0;
        __syncthreads();
        val += add; sh[tid] = val;
        __syncthreads();
    }
    if (tid == 255) g_bsum[blockIdx.x] = val;
    int run = val - s;
#pragma unroll
    for (int i = 0; i < 4; i++) {
        int idx = base + i;
        if (idx < N_NODES) g_rowptr[idx] = run;
        run += v[i];
    }
}

// scan3: per-block redundant scan of the 98 block sums, finalize rowptr+cursor.
__global__ void k_scan3() {
    __shared__ int sh[128];
    int tid = threadIdx.x;
    int val = 0;
    if (tid < 128) {
        val = (tid < NB_SCAN) ? g_bsum[tid] : 0;
        sh[tid] = val;
    }
    __syncthreads();
#pragma unroll
    for (int off = 1; off < 128; off <<= 1) {
        int add = (tid < 128 && tid >= off) ? sh[tid - off] : 0;
        __syncthreads();
        if (tid < 128) { val += add; sh[tid] = val; }
        __syncthreads();
    }
    int i = blockIdx.x * blockDim.x + tid;
    if (i < N_NODES) {
        int c = i / SCAN_CHUNK;
        int boff = (c == 0) ? 0 : sh[c - 1];
        int r = g_rowptr[i] + boff;
        g_rowptr[i] = r;
        g_cursor[i] = r;
    }
    if (i == 0) g_rowptr[N_NODES] = N_EDGES;
}

// fill: 8 edges/thread for deeper ATOMG MLP (latency-bound per ncu)
__global__ void k_fill(const int* __restrict__ src, const int* __restrict__ dst) {
    int t = blockIdx.x * blockDim.x + threadIdx.x;
    if (t >= N_EDGES / 8) return;
    int4 sa = reinterpret_cast<const int4*>(src)[2 * t];
    int4 sb = reinterpret_cast<const int4*>(src)[2 * t + 1];
    int4 da = reinterpret_cast<const int4*>(dst)[2 * t];
    int4 db = reinterpret_cast<const int4*>(dst)[2 * t + 1];
    int p0 = atomicAdd(&g_cursor[da.x], 1);
    int p1 = atomicAdd(&g_cursor[da.y], 1);
    int p2 = atomicAdd(&g_cursor[da.z], 1);
    int p3 = atomicAdd(&g_cursor[da.w], 1);
    int p4 = atomicAdd(&g_cursor[db.x], 1);
    int p5 = atomicAdd(&g_cursor[db.y], 1);
    int p6 = atomicAdd(&g_cursor[db.z], 1);
    int p7 = atomicAdd(&g_cursor[db.w], 1);
    g_col[p0] = sa.x; g_col[p1] = sa.y; g_col[p2] = sa.z; g_col[p3] = sa.w;
    g_col[p4] = sb.x; g_col[p5] = sb.y; g_col[p6] = sb.z; g_col[p7] = sb.w;
}

// ──────────── u = dinv ⊙ (x@W). 4 nodes × 10 classes per thread ────────────
// Computes dinv from g_deg directly (depends ONLY on k_deg → can overlap the
// CSR build on a second stream).
__global__ void __launch_bounds__(256) k_matmul(const float* __restrict__ x,
                                                const float* __restrict__ W) {
    __shared__ u64 Ws[N_FEAT * 20];  // [k][pair]: (W[k][2p], W[k][2p+1]) packed
    for (int i = threadIdx.x; i < N_FEAT * 20; i += blockDim.x)
        Ws[i] = reinterpret_cast<const u64*>(W)[i];  // float2 bits
    __syncthreads();

    int tid = threadIdx.x;
    int g  = tid & 3;         // class group: classes [10g, 10g+10)
    int ng = tid >> 2;        // node group within block (0..63)
    int n0 = blockIdx.x * 256 + ng * 4;
    if (n0 >= N_NODES) return;

    u64 acc[4][5];
#pragma unroll
    for (int i = 0; i < 4; i++)
#pragma unroll
        for (int p = 0; p < 5; p++) acc[i][p] = 0ull;

    const float4* xr[4];
#pragma unroll
    for (int i = 0; i < 4; i++) {
        int nr = n0 + i; if (nr >= N_NODES) nr = N_NODES - 1;
        xr[i] = reinterpret_cast<const float4*>(x + (size_t)nr * N_FEAT);
    }

    const u64* wg = Ws + 5 * g;
#pragma unroll 2
    for (int k4 = 0; k4 < N_FEAT / 4; k4++) {
        float4 xv[4];
#pragma unroll
        for (int i = 0; i < 4; i++) xv[i] = xr[i][k4];
#pragma unroll
        for (int j = 0; j < 4; j++) {
            int k = k4 * 4 + j;
            const u64* wk = wg + k * 20;
            u64 w0 = wk[0], w1 = wk[1], w2 = wk[2], w3 = wk[3], w4 = wk[4];
#pragma unroll
            for (int i = 0; i < 4; i++) {
                float f = (j == 0) ? xv[i].x : (j == 1) ? xv[i].y
                        : (j == 2) ? xv[i].z : xv[i].w;
                u64 f2 = pack2(f, f);
                FMA_F32X2(acc[i][0], f2, w0, acc[i][0]);
                FMA_F32X2(acc[i][1], f2, w1, acc[i][1]);
                FMA_F32X2(acc[i][2], f2, w2, acc[i][2]);
                FMA_F32X2(acc[i][3], f2, w3, acc[i][3]);
                FMA_F32X2(acc[i][4], f2, w4, acc[i][4]);
            }
        }
    }

#pragma unroll
    for (int i = 0; i < 4; i++) {
        int n = n0 + i;
        if (n >= N_NODES) break;
        float di = rsqrtf((float)(g_deg[n] + 1));  // same formula as scan1
        float2* row = reinterpret_cast<float2*>(g_u + (size_t)n * N_CLASSES + 10 * g);
#pragma unroll
        for (int p = 0; p < 5; p++) {
            float lo, hi;
            unpack2(acc[i][p], lo, hi);
            row[p] = make_float2(lo * di, hi * di);
        }
    }
}

// ──────── hop 1: g_t[n] = dinv^2 · (g_u[n] + Σ_{e∈row(n)} g_u[col[e]]) ─────
// Runs after the stream join (CSR + matmul both done). Also re-zeroes g_deg.
__global__ void __launch_bounds__(320) k_pull1() {
    const float4* uin = reinterpret_cast<const float4*>(g_u);
    int tid = threadIdx.x;
    int n = blockIdx.x * 32 + tid / 10;
    int j = tid % 10;

    if (j == 0) g_deg[n] = 0;   // restore for next invocation

    int r0 = g_rowptr[n];
    int r1 = g_rowptr[n + 1];

    float4 a0 = uin[n * C4 + j];  // self-loop term
    float4 a1 = make_float4(0.f, 0.f, 0.f, 0.f);
    float4 a2 = make_float4(0.f, 0.f, 0.f, 0.f);
    float4 a3 = make_float4(0.f, 0.f, 0.f, 0.f);

    int e = r0;
    for (; e + 4 <= r1; e += 4) {
        int c0 = g_col[e], c1 = g_col[e + 1], c2 = g_col[e + 2], c3 = g_col[e + 3];
        float4 v0 = uin[c0 * C4 + j];
        float4 v1 = uin[c1 * C4 + j];
        float4 v2 = uin[c2 * C4 + j];
        float4 v3 = uin[c3 * C4 + j];
        a0.x += v0.x; a0.y += v0.y; a0.z += v0.z; a0.w += v0.w;
        a1.x += v1.x; a1.y += v1.y; a1.z += v1.z; a1.w += v1.w;
        a2.x += v2.x; a2.y += v2.y; a2.z += v2.z; a2.w += v2.w;
        a3.x += v3.x; a3.y += v3.y; a3.z += v3.z; a3.w += v3.w;
    }
    for (; e < r1; e++) {
        int c = g_col[e];
        float4 v = uin[c * C4 + j];
        a0.x += v.x; a0.y += v.y; a0.z += v.z; a0.w += v.w;
    }
    float di = g_dinv[n];
    float sc = di * di;
    float4 r;
    r.x = ((a0.x + a1.x) + (a2.x + a3.x)) * sc;
    r.y = ((a0.y + a1.y) + (a2.y + a3.y)) * sc;
    r.z = ((a0.z + a1.z) + (a2.z + a3.z)) * sc;
    r.w = ((a0.w + a1.w) + (a2.w + a3.w)) * sc;
    reinterpret_cast<float4*>(g_t)[n * C4 + j] = r;
}

// ──── hop 2 + log-softmax fused: out[n] = lsm(dinv·(t_self+gather) + b) ────
__global__ void __launch_bounds__(320) k_pull2_lsm(const float* __restrict__ bias,
                                                   float* __restrict__ out) {
    __shared__ float bs[N_CLASSES];
    __shared__ float red[2][320];
    int tid = threadIdx.x;
    if (tid < N_CLASSES) bs[tid] = bias[tid];
    __syncthreads();

    const float4* uin = reinterpret_cast<const float4*>(g_t);
    int n = blockIdx.x * 32 + tid / 10;
    int j = tid % 10;

    int r0 = g_rowptr[n];
    int r1 = g_rowptr[n + 1];

    float4 a0 = uin[n * C4 + j];  // self-loop term
    float4 a1 = make_float4(0.f, 0.f, 0.f, 0.f);
    float4 a2 = make_float4(0.f, 0.f, 0.f, 0.f);
    float4 a3 = make_float4(0.f, 0.f, 0.f, 0.f);

    int e = r0;
    for (; e + 4 <= r1; e += 4) {
        int c0 = g_col[e], c1 = g_col[e + 1], c2 = g_col[e + 2], c3 = g_col[e + 3];
        float4 v0 = uin[c0 * C4 + j];
        float4 v1 = uin[c1 * C4 + j];
        float4 v2 = uin[c2 * C4 + j];
        float4 v3 = uin[c3 * C4 + j];
        a0.x += v0.x; a0.y += v0.y; a0.z += v0.z; a0.w += v0.w;
        a1.x += v1.x; a1.y += v1.y; a1.z += v1.z; a1.w += v1.w;
        a2.x += v2.x; a2.y += v2.y; a2.z += v2.z; a2.w += v2.w;
        a3.x += v3.x; a3.y += v3.y; a3.z += v3.z; a3.w += v3.w;
    }
    for (; e < r1; e++) {
        int c = g_col[e];
        float4 v = uin[c * C4 + j];
        a0.x += v.x; a0.y += v.y; a0.z += v.z; a0.w += v.w;
    }

    float di = g_dinv[n];
    float4 v;
    v.x = ((a0.x + a1.x) + (a2.x + a3.x)) * di + bs[4 * j + 0];
    v.y = ((a0.y + a1.y) + (a2.y + a3.y)) * di + bs[4 * j + 1];
    v.z = ((a0.z + a1.z) + (a2.z + a3.z)) * di + bs[4 * j + 2];
    v.w = ((a0.w + a1.w) + (a2.w + a3.w)) * di + bs[4 * j + 3];

    // log-softmax across the node's 10 threads via smem
    int base = (tid / 10) * 10;
    red[0][tid] = fmaxf(fmaxf(v.x, v.y), fmaxf(v.z, v.w));
    __syncthreads();
    float m = red[0][base];
#pragma unroll
    for (int k = 1; k < 10; k++) m = fmaxf(m, red[0][base + k]);
    red[1][tid] = __expf(v.x - m) + __expf(v.y - m) + __expf(v.z - m) + __expf(v.w - m);
    __syncthreads();
    float sum = 0.f;
#pragma unroll
    for (int k = 0; k < 10; k++) sum += red[1][base + k];
    float lse = m + __logf(sum);

    float4 o;
    o.x = v.x - lse; o.y = v.y - lse; o.z = v.z - lse; o.w = v.w - lse;
    reinterpret_cast<float4*>(out)[n * C4 + j] = o;
}

extern "C" void kernel_launch(void* const* d_in, const int* in_sizes, int n_in,
                              void* d_out, int out_size) {
    const float* x  = (const float*)d_in[0];  // [100000,128]
    const float* W  = (const float*)d_in[1];  // [128,40]
    const float* b  = (const float*)d_in[2];  // [40]
    const int*   ei = (const int*)d_in[3];    // [2,1600000]
    const int* src = ei;
    const int* dst = ei + N_EDGES;
    float* out = (float*)d_out;

    // One-time side-stream + events (host objects only; no device memory).
    static cudaStream_t s2 = [] {
        cudaStream_t s; cudaStreamCreateWithFlags(&s, cudaStreamNonBlocking); return s;
    }();
    static cudaEvent_t eFork = [] {
        cudaEvent_t e; cudaEventCreateWithFlags(&e, cudaEventDisableTiming); return e;
    }();
    static cudaEvent_t eJoin = [] {
        cudaEvent_t e; cudaEventCreateWithFlags(&e, cudaEventDisableTiming); return e;
    }();

    const int TB = 256;
    const int gN  = (N_NODES + TB - 1) / TB;
    const int gE8 = (N_EDGES / 8 + TB - 1) / TB;
    const int gMM = (N_NODES + 255) / 256;
    const int gP  = N_NODES / 32;   // 3125, exact

    // degree first (feeds both branches)
    k_deg<<<gE8, TB>>>(dst);

    // fork: matmul branch (needs only g_deg + inputs)
    cudaEventRecord(eFork, 0);
    cudaStreamWaitEvent(s2, eFork, 0);
    k_matmul<<<gMM, TB, 0, s2>>>(x, W);
    cudaEventRecord(eJoin, s2);

    // CSR branch on the capture stream
    k_scan1<<<NB_SCAN, 256>>>();
    k_scan3<<<gN, TB>>>();
    k_fill<<<gE8, TB>>>(src, dst);

    // join, then the two pull hops
    cudaStreamWaitEvent(0, eJoin, 0);
    k_pull1<<<gP, 320>>>();             // g_u -> g_t, ×dinv^2 (+deg re-zero)
    k_pull2_lsm<<<gP, 320>>>(b, out);   // g_t -> out, fused log-softmax
}

// round 15
// speedup vs baseline: 2.6453x; 1.0852x over previous
#include <cuda_runtime.h>
#include <cuda_fp16.h>

#define N_NODES   100000
#define N_FEAT    128
#define N_CLASSES 40
#define NU        20   // u32 (half2) per 40-class row
#define N_EDGES   1600000
#define SCAN_CHUNK 1024
#define NB_SCAN   ((N_NODES + SCAN_CHUNK - 1) / SCAN_CHUNK)  // 98

typedef unsigned long long u64;
typedef unsigned int       u32;

// Scratch (static device globals — no allocation anywhere).
// g_deg starts zeroed (module init) and is re-zeroed by k_pull1 every call.
__device__ u32   g_u[N_NODES * NU];   // fp16 payload ping
__device__ u32   g_t[N_NODES * NU];   // fp16 payload pong
__device__ float g_dinv[N_NODES];
__device__ int   g_deg[N_NODES];
__device__ int   g_rowptr[N_NODES + 1];
__device__ int   g_cursor[N_NODES];
__device__ int   g_col[N_EDGES];
__device__ int   g_bsum[NB_SCAN];

__device__ __forceinline__ u64 pack2(float a, float b) {
    u64 p; asm("mov.b64 %0, {%1, %2};" : "=l"(p) : "f"(a), "f"(b)); return p;
}
__device__ __forceinline__ void unpack2(u64 p, float& a, float& b) {
    asm("mov.b64 {%0, %1}, %2;" : "=f"(a), "=f"(b) : "l"(p));
}
#define FMA_F32X2(d, a, b, c) \
    asm("fma.rn.f32x2 %0, %1, %2, %3;" : "=l"(d) : "l"(a), "l"(b), "l"(c))

__device__ __forceinline__ u32 f22h(float a, float b) {
    __half2 h = __floats2half2_rn(a, b);
    return *reinterpret_cast<u32*>(&h);
}
__device__ __forceinline__ float2 h22f(u32 u) {
    __half2 h = *reinterpret_cast<__half2*>(&u);
    return __half22float2(h);
}

// ─────────── degree (deg assumed 0 at entry); 8 edges/thread ───────────────
__global__ void k_deg(const int* __restrict__ dst) {
    int t = blockIdx.x * blockDim.x + threadIdx.x;
    if (t < N_EDGES / 8) {
        int4 a = reinterpret_cast<const int4*>(dst)[2 * t];
        int4 b = reinterpret_cast<const int4*>(dst)[2 * t + 1];
        atomicAdd(&g_deg[a.x], 1); atomicAdd(&g_deg[a.y], 1);
        atomicAdd(&g_deg[a.z], 1); atomicAdd(&g_deg[a.w], 1);
        atomicAdd(&g_deg[b.x], 1); atomicAdd(&g_deg[b.y], 1);
        atomicAdd(&g_deg[b.z], 1); atomicAdd(&g_deg[b.w], 1);
    }
}

// ─────────────── CSR build: scan1 (dinv fused) ─────────────────────────────
__global__ void k_scan1() {
    __shared__ int sh[256];
    int tid = threadIdx.x;
    int base = blockIdx.x * SCAN_CHUNK + tid * 4;
    int v[4]; int s = 0;
#pragma unroll
    for (int i = 0; i < 4; i++) {
        int idx = base + i;
        v[i] = (idx < N_NODES) ? g_deg[idx] : 0;
        if (idx < N_NODES) g_dinv[idx] = rsqrtf((float)(v[i] + 1));  // +1 self loop
        s += v[i];
    }
    int val = s;
    sh[tid] = val; __syncthreads();
#pragma unroll
    for (int off = 1; off < 256; off <<= 1) {
        int add = (tid >= off) ? sh[tid - off] : 0;
        __syncthreads();
        val += add; sh[tid] = val;
        __syncthreads();
    }
    if (tid == 255) g_bsum[blockIdx.x] = val;
    int run = val - s;
#pragma unroll
    for (int i = 0; i < 4; i++) {
        int idx = base + i;
        if (idx < N_NODES) g_rowptr[idx] = run;
        run += v[i];
    }
}

// scan3: per-block redundant scan of the 98 block sums, finalize rowptr+cursor.
__global__ void k_scan3() {
    __shared__ int sh[128];
    int tid = threadIdx.x;
    int val = 0;
    if (tid < 128) {
        val = (tid < NB_SCAN) ? g_bsum[tid] : 0;
        sh[tid] = val;
    }
    __syncthreads();
#pragma unroll
    for (int off = 1; off < 128; off <<= 1) {
        int add = (tid < 128 && tid >= off) ? sh[tid - off] : 0;
        __syncthreads();
        if (tid < 128) { val += add; sh[tid] = val; }
        __syncthreads();
    }
    int i = blockIdx.x * blockDim.x + tid;
    if (i < N_NODES) {
        int c = i / SCAN_CHUNK;
        int boff = (c == 0) ? 0 : sh[c - 1];
        int r = g_rowptr[i] + boff;
        g_rowptr[i] = r;
        g_cursor[i] = r;
    }
    if (i == 0) g_rowptr[N_NODES] = N_EDGES;
}

// fill: 8 edges/thread for deeper ATOMG MLP
__global__ void k_fill(const int* __restrict__ src, const int* __restrict__ dst) {
    int t = blockIdx.x * blockDim.x + threadIdx.x;
    if (t >= N_EDGES / 8) return;
    int4 sa = reinterpret_cast<const int4*>(src)[2 * t];
    int4 sb = reinterpret_cast<const int4*>(src)[2 * t + 1];
    int4 da = reinterpret_cast<const int4*>(dst)[2 * t];
    int4 db = reinterpret_cast<const int4*>(dst)[2 * t + 1];
    int p0 = atomicAdd(&g_cursor[da.x], 1);
    int p1 = atomicAdd(&g_cursor[da.y], 1);
    int p2 = atomicAdd(&g_cursor[da.z], 1);
    int p3 = atomicAdd(&g_cursor[da.w], 1);
    int p4 = atomicAdd(&g_cursor[db.x], 1);
    int p5 = atomicAdd(&g_cursor[db.y], 1);
    int p6 = atomicAdd(&g_cursor[db.z], 1);
    int p7 = atomicAdd(&g_cursor[db.w], 1);
    g_col[p0] = sa.x; g_col[p1] = sa.y; g_col[p2] = sa.z; g_col[p3] = sa.w;
    g_col[p4] = sb.x; g_col[p5] = sb.y; g_col[p6] = sb.z; g_col[p7] = sb.w;
}

// ─────── u = fp16(dinv ⊙ (x@W)). 4 nodes × 10 classes per thread ───────────
// dinv computed from g_deg (depends only on k_deg → overlaps the CSR build).
__global__ void __launch_bounds__(256) k_matmul(const float* __restrict__ x,
                                                const float* __restrict__ W) {
    __shared__ u64 Ws[N_FEAT * 20];  // [k][pair]: (W[k][2p], W[k][2p+1]) packed
    for (int i = threadIdx.x; i < N_FEAT * 20; i += blockDim.x)
        Ws[i] = reinterpret_cast<const u64*>(W)[i];  // float2 bits
    __syncthreads();

    int tid = threadIdx.x;
    int g  = tid & 3;         // class group: classes [10g, 10g+10)
    int ng = tid >> 2;        // node group within block (0..63)
    int n0 = blockIdx.x * 256 + ng * 4;
    if (n0 >= N_NODES) return;

    u64 acc[4][5];
#pragma unroll
    for (int i = 0; i < 4; i++)
#pragma unroll
        for (int p = 0; p < 5; p++) acc[i][p] = 0ull;

    const float4* xr[4];
#pragma unroll
    for (int i = 0; i < 4; i++) {
        int nr = n0 + i; if (nr >= N_NODES) nr = N_NODES - 1;
        xr[i] = reinterpret_cast<const float4*>(x + (size_t)nr * N_FEAT);
    }

    const u64* wg = Ws + 5 * g;
#pragma unroll 2
    for (int k4 = 0; k4 < N_FEAT / 4; k4++) {
        float4 xv[4];
#pragma unroll
        for (int i = 0; i < 4; i++) xv[i] = xr[i][k4];
#pragma unroll
        for (int j = 0; j < 4; j++) {
            int k = k4 * 4 + j;
            const u64* wk = wg + k * 20;
            u64 w0 = wk[0], w1 = wk[1], w2 = wk[2], w3 = wk[3], w4 = wk[4];
#pragma unroll
            for (int i = 0; i < 4; i++) {
                float f = (j == 0) ? xv[i].x : (j == 1) ? xv[i].y
                        : (j == 2) ? xv[i].z : xv[i].w;
                u64 f2 = pack2(f, f);
                FMA_F32X2(acc[i][0], f2, w0, acc[i][0]);
                FMA_F32X2(acc[i][1], f2, w1, acc[i][1]);
                FMA_F32X2(acc[i][2], f2, w2, acc[i][2]);
                FMA_F32X2(acc[i][3], f2, w3, acc[i][3]);
                FMA_F32X2(acc[i][4], f2, w4, acc[i][4]);
            }
        }
    }

#pragma unroll
    for (int i = 0; i < 4; i++) {
        int n = n0 + i;
        if (n >= N_NODES) break;
        float di = rsqrtf((float)(g_deg[n] + 1));  // same formula as scan1
        u32* row = g_u + (size_t)n * NU + 5 * g;
#pragma unroll
        for (int p = 0; p < 5; p++) {
            float lo, hi;
            unpack2(acc[i][p], lo, hi);
            row[p] = f22h(lo * di, hi * di);
        }
    }
}

// ──────── hop 1: g_t[n] = fp16( dinv² · (u[n] + Σ u[col[e]]) ) ─────────────
// 10 threads/node, one uint2 (4 classes) each; 320-thread blocks = 32 nodes;
// 3125 blocks exactly cover 100000 nodes. fp32 accumulation.
__global__ void __launch_bounds__(320) k_pull1() {
    const uint2* uin = reinterpret_cast<const uint2*>(g_u);
    int tid = threadIdx.x;
    int n = blockIdx.x * 32 + tid / 10;
    int j = tid % 10;

    if (j == 0) g_deg[n] = 0;   // restore for next invocation

    int r0 = g_rowptr[n];
    int r1 = g_rowptr[n + 1];

    uint2 s = uin[n * 10 + j];  // self-loop term
    float2 a0 = h22f(s.x), a1 = h22f(s.y);
    float2 b0 = {0.f, 0.f}, b1 = {0.f, 0.f};
    float2 c0_ = {0.f, 0.f}, c1_ = {0.f, 0.f};
    float2 d0 = {0.f, 0.f}, d1 = {0.f, 0.f};

    int e = r0;
    for (; e + 4 <= r1; e += 4) {
        int q0 = g_col[e], q1 = g_col[e + 1], q2 = g_col[e + 2], q3 = g_col[e + 3];
        uint2 v0 = uin[q0 * 10 + j];
        uint2 v1 = uin[q1 * 10 + j];
        uint2 v2 = uin[q2 * 10 + j];
        uint2 v3 = uin[q3 * 10 + j];
        float2 t;
        t = h22f(v0.x); a0.x += t.x; a0.y += t.y;
        t = h22f(v0.y); a1.x += t.x; a1.y += t.y;
        t = h22f(v1.x); b0.x += t.x; b0.y += t.y;
        t = h22f(v1.y); b1.x += t.x; b1.y += t.y;
        t = h22f(v2.x); c0_.x += t.x; c0_.y += t.y;
        t = h22f(v2.y); c1_.x += t.x; c1_.y += t.y;
        t = h22f(v3.x); d0.x += t.x; d0.y += t.y;
        t = h22f(v3.y); d1.x += t.x; d1.y += t.y;
    }
    for (; e < r1; e++) {
        int c = g_col[e];
        uint2 v = uin[c * 10 + j];
        float2 t;
        t = h22f(v.x); a0.x += t.x; a0.y += t.y;
        t = h22f(v.y); a1.x += t.x; a1.y += t.y;
    }
    float di = g_dinv[n];
    float sc = di * di;
    float s0 = ((a0.x + b0.x) + (c0_.x + d0.x)) * sc;
    float s1 = ((a0.y + b0.y) + (c0_.y + d0.y)) * sc;
    float s2 = ((a1.x + b1.x) + (c1_.x + d1.x)) * sc;
    float s3 = ((a1.y + b1.y) + (c1_.y + d1.y)) * sc;
    uint2 o;
    o.x = f22h(s0, s1);
    o.y = f22h(s2, s3);
    reinterpret_cast<uint2*>(g_t)[n * 10 + j] = o;
}

// ──── hop 2 + log-softmax fused: out[n] = lsm(dinv·(t_self+gather) + b) ────
__global__ void __launch_bounds__(320) k_pull2_lsm(const float* __restrict__ bias,
                                                   float* __restrict__ out) {
    __shared__ float bs[N_CLASSES];
    __shared__ float red[2][320];
    int tid = threadIdx.x;
    if (tid < N_CLASSES) bs[tid] = bias[tid];
    __syncthreads();

    const uint2* uin = reinterpret_cast<const uint2*>(g_t);
    int n = blockIdx.x * 32 + tid / 10;
    int j = tid % 10;

    int r0 = g_rowptr[n];
    int r1 = g_rowptr[n + 1];

    uint2 s = uin[n * 10 + j];  // self-loop term
    float2 a0 = h22f(s.x), a1 = h22f(s.y);
    float2 b0 = {0.f, 0.f}, b1 = {0.f, 0.f};
    float2 c0_ = {0.f, 0.f}, c1_ = {0.f, 0.f};
    float2 d0 = {0.f, 0.f}, d1 = {0.f, 0.f};

    int e = r0;
    for (; e + 4 <= r1; e += 4) {
        int q0 = g_col[e], q1 = g_col[e + 1], q2 = g_col[e + 2], q3 = g_col[e + 3];
        uint2 v0 = uin[q0 * 10 + j];
        uint2 v1 = uin[q1 * 10 + j];
        uint2 v2 = uin[q2 * 10 + j];
        uint2 v3 = uin[q3 * 10 + j];
        float2 t;
        t = h22f(v0.x); a0.x += t.x; a0.y += t.y;
        t = h22f(v0.y); a1.x += t.x; a1.y += t.y;
        t = h22f(v1.x); b0.x += t.x; b0.y += t.y;
        t = h22f(v1.y); b1.x += t.x; b1.y += t.y;
        t = h22f(v2.x); c0_.x += t.x; c0_.y += t.y;
        t = h22f(v2.y); c1_.x += t.x; c1_.y += t.y;
        t = h22f(v3.x); d0.x += t.x; d0.y += t.y;
        t = h22f(v3.y); d1.x += t.x; d1.y += t.y;
    }
    for (; e < r1; e++) {
        int c = g_col[e];
        uint2 v = uin[c * 10 + j];
        float2 t;
        t = h22f(v.x); a0.x += t.x; a0.y += t.y;
        t = h22f(v.y); a1.x += t.x; a1.y += t.y;
    }

    float di = g_dinv[n];
    float4 v;
    v.x = ((a0.x + b0.x) + (c0_.x + d0.x)) * di + bs[4 * j + 0];
    v.y = ((a0.y + b0.y) + (c0_.y + d0.y)) * di + bs[4 * j + 1];
    v.z = ((a1.x + b1.x) + (c1_.x + d1.x)) * di + bs[4 * j + 2];
    v.w = ((a1.y + b1.y) + (c1_.y + d1.y)) * di + bs[4 * j + 3];

    // log-softmax across the node's 10 threads via smem
    int base = (tid / 10) * 10;
    red[0][tid] = fmaxf(fmaxf(v.x, v.y), fmaxf(v.z, v.w));
    __syncthreads();
    float m = red[0][base];
#pragma unroll
    for (int k = 1; k < 10; k++) m = fmaxf(m, red[0][base + k]);
    red[1][tid] = __expf(v.x - m) + __expf(v.y - m) + __expf(v.z - m) + __expf(v.w - m);
    __syncthreads();
    float sum = 0.f;
#pragma unroll
    for (int k = 0; k < 10; k++) sum += red[1][base + k];
    float lse = m + __logf(sum);

    float4 o;
    o.x = v.x - lse; o.y = v.y - lse; o.z = v.z - lse; o.w = v.w - lse;
    reinterpret_cast<float4*>(out)[n * 10 + j] = o;
}

extern "C" void kernel_launch(void* const* d_in, const int* in_sizes, int n_in,
                              void* d_out, int out_size) {
    const float* x  = (const float*)d_in[0];  // [100000,128]
    const float* W  = (const float*)d_in[1];  // [128,40]
    const float* b  = (const float*)d_in[2];  // [40]
    const int*   ei = (const int*)d_in[3];    // [2,1600000]
    const int* src = ei;
    const int* dst = ei + N_EDGES;
    float* out = (float*)d_out;

    // One-time side-stream + events (host objects only; no device memory).
    static cudaStream_t s2 = [] {
        cudaStream_t s; cudaStreamCreateWithFlags(&s, cudaStreamNonBlocking); return s;
    }();
    static cudaEvent_t eFork = [] {
        cudaEvent_t e; cudaEventCreateWithFlags(&e, cudaEventDisableTiming); return e;
    }();
    static cudaEvent_t eJoin = [] {
        cudaEvent_t e; cudaEventCreateWithFlags(&e, cudaEventDisableTiming); return e;
    }();

    const int TB = 256;
    const int gN  = (N_NODES + TB - 1) / TB;
    const int gE8 = (N_EDGES / 8 + TB - 1) / TB;
    const int gMM = (N_NODES + 255) / 256;
    const int gP  = N_NODES / 32;   // 3125, exact

    // degree first (feeds both branches)
    k_deg<<<gE8, TB>>>(dst);

    // fork: matmul branch (needs only g_deg + inputs)
    cudaEventRecord(eFork, 0);
    cudaStreamWaitEvent(s2, eFork, 0);
    k_matmul<<<gMM, TB, 0, s2>>>(x, W);
    cudaEventRecord(eJoin, s2);

    // CSR branch on the capture stream
    k_scan1<<<NB_SCAN, 256>>>();
    k_scan3<<<gN, TB>>>();
    k_fill<<<gE8, TB>>>(src, dst);

    // join, then the two pull hops
    cudaStreamWaitEvent(0, eJoin, 0);
    k_pull1<<<gP, 320>>>();             // g_u -> g_t (fp16), ×dinv², +deg re-zero
    k_pull2_lsm<<<gP, 320>>>(b, out);   // g_t -> out, fused log-softmax
}